// round 17
// baseline (speedup 1.0000x reference)
#include <cuda_runtime.h>
#include <cuda_bf16.h>
#include <math.h>
#include <stdint.h>

// Problem constants
#define NN    8192
#define D_IN  512
#define HH    256
#define EE    262144
#define NL    2
#define LN_EPS 1e-5f
#define BCAP  128      // per-node bucket capacity (max deg ~60)

// ---------------- device scratch (no allocations allowed) ----------------
__device__ __nv_bfloat16 g_hwb[NN * HH];        // hw bf16 for gathers
__device__ __nv_bfloat16 g_Ah[NN * D_IN];       // x split hi
__device__ __nv_bfloat16 g_Al[NN * D_IN];       // x split lo
__device__ __nv_bfloat16 g_Ah2[NN * HH];        // h split hi
__device__ __nv_bfloat16 g_Al2[NN * HH];        // h split lo
__device__ __nv_bfloat16 g_Bh[D_IN * HH + NL * HH * HH];  // weights hi
__device__ __nv_bfloat16 g_Bl[D_IN * HH + NL * HH * HH];  // weights lo
__device__ float g_s_srcp[4 * NN];              // score partials (per N-quarter)
__device__ float g_s_tgtp[4 * NN];
__device__ float g_s_src[NN];                   // combined scores
__device__ float g_s_tgt[NN];
__device__ int   g_cnt[NN];
__device__ int   g_bkt[NN * BCAP];              // per-node target buckets
__device__ float g_colsum_part[64 * HH];        // per M-CTA column partials
__device__ float g_colsum[HH];
__device__ float g_pool_part[64 * HH];

// ---------------- HMMA GEMM: C[8192 x 256] = A * B^T ---------------------
// Block tile 128x64, 256 threads (8 warps, 4m x 2n), warp tile 32x32.
// grid (64, 4). bf16 split inputs, 3 passes, fp32 accum.
// cp.async 2-stage pipeline, ldmatrix fragments.
#define SROW   40                       // smem row stride (bf16 elems)
#define ATILEB (128 * SROW * 2)         // 10240 bytes (A tile, 128 rows)
#define BTILEB (64 * SROW * 2)          // 5120 bytes  (B tile, 64 rows)
#define STAGEB (2 * ATILEB + 2 * BTILEB) // 30720 bytes per stage
#define OFF_AH 0
#define OFF_AL ATILEB
#define OFF_BH (2 * ATILEB)
#define OFF_BL (2 * ATILEB + BTILEB)
#define SMEM_DYN (2 * STAGEB)           // 61440 bytes

__device__ __forceinline__ uint32_t smem_u32(const void* p) {
    uint32_t a;
    asm("{ .reg .u64 t; cvta.to.shared.u64 t, %1; cvt.u32.u64 %0, t; }"
        : "=r"(a) : "l"(p));
    return a;
}
__device__ __forceinline__ void cp16(uint32_t saddr, const void* gptr) {
    asm volatile("cp.async.cg.shared.global [%0], [%1], 16;"
                 :: "r"(saddr), "l"(gptr));
}
#define CP_COMMIT() asm volatile("cp.async.commit_group;" ::: "memory")
#define CP_WAIT(n)  asm volatile("cp.async.wait_group %0;" :: "n"(n) : "memory")
__device__ __forceinline__ void ldsm4(uint32_t* r, uint32_t addr) {
    asm volatile("ldmatrix.sync.aligned.m8n8.x4.shared.b16 {%0,%1,%2,%3}, [%4];"
                 : "=r"(r[0]), "=r"(r[1]), "=r"(r[2]), "=r"(r[3]) : "r"(addr));
}
__device__ __forceinline__ void mma_bf16(float* d, const uint32_t* a, const uint32_t* b) {
    asm volatile(
        "mma.sync.aligned.m16n8k16.row.col.f32.bf16.bf16.f32 "
        "{%0,%1,%2,%3}, {%4,%5,%6,%7}, {%8,%9}, {%0,%1,%2,%3};"
        : "+f"(d[0]), "+f"(d[1]), "+f"(d[2]), "+f"(d[3])
        : "r"(a[0]), "r"(a[1]), "r"(a[2]), "r"(a[3]), "r"(b[0]), "r"(b[1]));
}

__global__ __launch_bounds__(256)
void gemm_mma(const __nv_bfloat16* __restrict__ Ah, const __nv_bfloat16* __restrict__ Al,
              const __nv_bfloat16* __restrict__ Bh, const __nv_bfloat16* __restrict__ Bl,
              const float* __restrict__ bias, float* __restrict__ Cf,
              __nv_bfloat16* __restrict__ Chi, __nv_bfloat16* __restrict__ Clo,
              __nv_bfloat16* __restrict__ Cb,
              const float* __restrict__ a_att,   // non-null => attn epilogue
              int K) {
    extern __shared__ char smem[];
    uint32_t sb = smem_u32(smem);
    int tid = threadIdx.x;
    int wid = tid >> 5, lane = tid & 31;
    int wm = wid >> 1, wn = wid & 1;          // 4m x 2n warp grid
    int bm = blockIdx.x * 128;
    int bn = blockIdx.y * 64;

    float acc[2][4][4];
#pragma unroll
    for (int mt = 0; mt < 2; mt++)
#pragma unroll
        for (int nt = 0; nt < 4; nt++)
#pragma unroll
            for (int q = 0; q < 4; q++) acc[mt][nt][q] = 0.f;

    const int NCH = K >> 5;

    // loaders: A tile = 512 16B vecs (2/thread), B tile = 256 vecs (1/thread)
    int arA = tid >> 2, auA = tid & 3;
    size_t gaB0 = (size_t)(bm + arA) * K + auA * 8;
    size_t gaB1 = (size_t)(bm + 64 + arA) * K + auA * 8;
    uint32_t soA0 = (uint32_t)(arA * SROW + auA * 8) * 2;
    uint32_t soA1 = (uint32_t)((64 + arA) * SROW + auA * 8) * 2;
    size_t gbB = (size_t)(bn + arA) * K + auA * 8;
    uint32_t soB = soA0;

    // prologue: stage 0
    {
        cp16(sb + OFF_AH + soA0, Ah + gaB0);
        cp16(sb + OFF_AH + soA1, Ah + gaB1);
        cp16(sb + OFF_AL + soA0, Al + gaB0);
        cp16(sb + OFF_AL + soA1, Al + gaB1);
        cp16(sb + OFF_BH + soB, Bh + gbB);
        cp16(sb + OFF_BL + soB, Bl + gbB);
        CP_COMMIT();
    }

    for (int kc = 0; kc < NCH; kc++) {
        bool has = (kc + 1) < NCH;
        if (has) {
            uint32_t st = sb + ((kc + 1) & 1) * STAGEB;
            int k0 = (kc + 1) * 32;
            cp16(st + OFF_AH + soA0, Ah + gaB0 + k0);
            cp16(st + OFF_AH + soA1, Ah + gaB1 + k0);
            cp16(st + OFF_AL + soA0, Al + gaB0 + k0);
            cp16(st + OFF_AL + soA1, Al + gaB1 + k0);
            cp16(st + OFF_BH + soB, Bh + gbB + k0);
            cp16(st + OFF_BL + soB, Bl + gbB + k0);
            CP_COMMIT();
            CP_WAIT(1);
        } else {
            CP_WAIT(0);
        }
        __syncthreads();
        uint32_t st = sb + (kc & 1) * STAGEB;
#pragma unroll
        for (int ks = 0; ks < 2; ks++) {
            int ac = ks * 16;
            uint32_t ah[2][4], al[2][4], bh[4][2], bl[4][2];
            {
                int arow = (lane & 15);
                int acol = ac + (lane >> 4) * 8;
#pragma unroll
                for (int mt = 0; mt < 2; mt++) {
                    int r = wm * 32 + mt * 16 + arow;
                    uint32_t off = (uint32_t)(r * SROW + acol) * 2;
                    ldsm4(ah[mt], st + OFF_AH + off);
                    ldsm4(al[mt], st + OFF_AL + off);
                }
            }
            {
                int brow = ((lane >> 4) & 1) * 8 + (lane & 7);
                int bcol = ac + ((lane >> 3) & 1) * 8;
#pragma unroll
                for (int np = 0; np < 2; np++) {
                    int n = wn * 32 + np * 16 + brow;
                    uint32_t off = (uint32_t)(n * SROW + bcol) * 2;
                    uint32_t t4[4];
                    ldsm4(t4, st + OFF_BH + off);
                    bh[2 * np][0] = t4[0]; bh[2 * np][1] = t4[1];
                    bh[2 * np + 1][0] = t4[2]; bh[2 * np + 1][1] = t4[3];
                    ldsm4(t4, st + OFF_BL + off);
                    bl[2 * np][0] = t4[0]; bl[2 * np][1] = t4[1];
                    bl[2 * np + 1][0] = t4[2]; bl[2 * np + 1][1] = t4[3];
                }
            }
#pragma unroll
            for (int mt = 0; mt < 2; mt++)
#pragma unroll
                for (int nt = 0; nt < 4; nt++) {
                    mma_bf16(acc[mt][nt], ah[mt], bh[nt]);
                    mma_bf16(acc[mt][nt], ah[mt], bl[nt]);
                    mma_bf16(acc[mt][nt], al[mt], bh[nt]);
                }
        }
        __syncthreads();
    }

    // ---- main output stores ----
#pragma unroll
    for (int mt = 0; mt < 2; mt++) {
#pragma unroll
        for (int nt = 0; nt < 4; nt++) {
            int r0 = bm + wm * 32 + mt * 16 + (lane >> 2);
            int c0 = bn + wn * 32 + nt * 8 + (lane & 3) * 2;
#pragma unroll
            for (int q = 0; q < 4; q++) {
                int row = r0 + (q >> 1) * 8;
                int col = c0 + (q & 1);
                float v = acc[mt][nt][q];
                if (bias) { v += bias[col]; acc[mt][nt][q] = v; }
                size_t o = (size_t)row * HH + col;
                if (Cf) Cf[o] = v;
                if (Chi) {
                    __nv_bfloat16 hb = __float2bfloat16(v);
                    Chi[o] = hb;
                    Clo[o] = __float2bfloat16(v - __bfloat162float(hb));
                }
                if (Cb) Cb[o] = __float2bfloat16(v);
            }
        }
    }

    // ---- fused attention-prep epilogue (layer GEMMs only) ----
    if (a_att) {
        float colp[8];
#pragma unroll
        for (int j = 0; j < 8; j++) colp[j] = 0.f;
#pragma unroll
        for (int mt = 0; mt < 2; mt++)
#pragma unroll
            for (int nt = 0; nt < 4; nt++)
#pragma unroll
                for (int q = 0; q < 4; q++)
                    colp[nt * 2 + (q & 1)] += acc[mt][nt][q];
#pragma unroll
        for (int off = 4; off <= 16; off <<= 1)
#pragma unroll
            for (int j = 0; j < 8; j++)
                colp[j] += __shfl_xor_sync(0xffffffffu, colp[j], off);

        float a_s[8], a_t[8];
#pragma unroll
        for (int nt = 0; nt < 4; nt++)
#pragma unroll
            for (int qb = 0; qb < 2; qb++) {
                int col = bn + wn * 32 + nt * 8 + (lane & 3) * 2 + qb;
                a_s[nt * 2 + qb] = __ldg(a_att + col);
                a_t[nt * 2 + qb] = __ldg(a_att + HH + col);
            }
        float rs_[4], rt_[4];
#pragma unroll
        for (int j = 0; j < 4; j++) { rs_[j] = 0.f; rt_[j] = 0.f; }
#pragma unroll
        for (int mt = 0; mt < 2; mt++)
#pragma unroll
            for (int nt = 0; nt < 4; nt++)
#pragma unroll
                for (int q = 0; q < 4; q++) {
                    float v = acc[mt][nt][q];
                    rs_[mt * 2 + (q >> 1)] += v * a_s[nt * 2 + (q & 1)];
                    rt_[mt * 2 + (q >> 1)] += v * a_t[nt * 2 + (q & 1)];
                }
#pragma unroll
        for (int off = 1; off <= 2; off <<= 1)
#pragma unroll
            for (int j = 0; j < 4; j++) {
                rs_[j] += __shfl_xor_sync(0xffffffffu, rs_[j], off);
                rt_[j] += __shfl_xor_sync(0xffffffffu, rt_[j], off);
            }

        float* sS = (float*)smem;
        float* sT = sS + 256;
        float* sC = sT + 256;
        if ((lane & 3) == 0) {
#pragma unroll
            for (int mt = 0; mt < 2; mt++)
#pragma unroll
                for (int rq = 0; rq < 2; rq++) {
                    int row = wm * 32 + mt * 16 + rq * 8 + (lane >> 2);
                    sS[wn * 128 + row] = rs_[mt * 2 + rq];
                    sT[wn * 128 + row] = rt_[mt * 2 + rq];
                }
        }
        if (lane < 4) {
#pragma unroll
            for (int nt = 0; nt < 4; nt++)
#pragma unroll
                for (int qb = 0; qb < 2; qb++)
                    sC[wid * 32 + nt * 8 + lane * 2 + qb] = colp[nt * 2 + qb];
        }
        __syncthreads();
        if (tid < 128) {
            float ss = sS[tid] + sS[128 + tid];
            float tt = sT[tid] + sT[128 + tid];
            g_s_srcp[blockIdx.y * NN + bm + tid] = ss;
            g_s_tgtp[blockIdx.y * NN + bm + tid] = tt;
        } else if (tid < 192) {
            int c = tid - 128;
            int wnc = c >> 5, ci = c & 31;
            float cv = sC[(0 * 2 + wnc) * 32 + ci] + sC[(1 * 2 + wnc) * 32 + ci]
                     + sC[(2 * 2 + wnc) * 32 + ci] + sC[(3 * 2 + wnc) * 32 + ci];
            g_colsum_part[blockIdx.x * HH + bn + c] = cv;
        }
    }
}

// ---------------- prep: split x, split weights, zero counters ------------
__global__ void prep_kernel(const float* __restrict__ x,
                            const float* __restrict__ W_in,
                            const float* __restrict__ W_gat) {
    const int NW = D_IN * HH + NL * HH * HH;
    for (int i = blockIdx.x * blockDim.x + threadIdx.x; i < NN * D_IN;
         i += gridDim.x * blockDim.x) {
        float v = x[i];
        __nv_bfloat16 hb = __float2bfloat16(v);
        g_Ah[i] = hb;
        g_Al[i] = __float2bfloat16(v - __bfloat162float(hb));
        if (i < NW) {
            float w = (i < D_IN * HH) ? W_in[i] : W_gat[i - D_IN * HH];
            __nv_bfloat16 wb = __float2bfloat16(w);
            g_Bh[i] = wb;
            g_Bl[i] = __float2bfloat16(w - __bfloat162float(wb));
        }
        if (i < NN) g_cnt[i] = 0;
    }
}

// ---------------- bucket scatter + per-node sort --------------------------
__global__ void scatter_kernel(const int* __restrict__ ei) {
    const int* src = ei;
    const int* tgt = ei + EE;
    for (int k = blockIdx.x * blockDim.x + threadIdx.x; k < EE;
         k += gridDim.x * blockDim.x) {
        int s = src[k];
        int pos = atomicAdd(&g_cnt[s], 1);
        if (pos < BCAP) g_bkt[s * BCAP + pos] = tgt[k];
    }
}

__global__ __launch_bounds__(256)
void sort_bkt_kernel() {
    __shared__ int buf[8][BCAP];
    int wid = threadIdx.x >> 5, lane = threadIdx.x & 31;
    int i = blockIdx.x * 8 + wid;
    int deg = min(g_cnt[i], BCAP);
    for (int j = lane; j < deg; j += 32) buf[wid][j] = g_bkt[i * BCAP + j];
    __syncwarp();
    for (int p = 0; p < deg; p++) {
        int start = p & 1;
        for (int j = lane; 2 * j + start + 1 < deg; j += 32) {
            int a = buf[wid][2 * j + start], b = buf[wid][2 * j + start + 1];
            if (a > b) { buf[wid][2 * j + start] = b; buf[wid][2 * j + start + 1] = a; }
        }
        __syncwarp();
    }
    for (int j = lane; j < deg; j += 32) g_bkt[i * BCAP + j] = buf[wid][j];
}

// ---------------- colsum finalize + score combine (one kernel) ------------
__global__ void finalize_kernel() {
    if (blockIdx.x == 0) {
        int c = threadIdx.x;
        float s = 0.f;
#pragma unroll
        for (int b = 0; b < 64; b++) s += g_colsum_part[b * HH + c];
        g_colsum[c] = s;
    } else {
        int i = (blockIdx.x - 1) * 256 + threadIdx.x;
        g_s_src[i] = g_s_srcp[i] + g_s_srcp[NN + i] + g_s_srcp[2 * NN + i] + g_s_srcp[3 * NN + i];
        g_s_tgt[i] = g_s_tgtp[i] + g_s_tgtp[NN + i] + g_s_tgtp[2 * NN + i] + g_s_tgtp[3 * NN + i];
    }
}

// ---------------- warp-per-node aggregate + residual + LN + ELU ----------
__device__ __forceinline__ float4 unp_bf4u(uint32_t lo, uint32_t hi) {
    __nv_bfloat162 a = *reinterpret_cast<__nv_bfloat162*>(&lo);
    __nv_bfloat162 b = *reinterpret_cast<__nv_bfloat162*>(&hi);
    float2 fa = __bfloat1622float2(a), fb = __bfloat1622float2(b);
    return make_float4(fa.x, fa.y, fb.x, fb.y);
}

__global__ __launch_bounds__(256)
void aggregate_kernel(float* __restrict__ h,
                      const float* __restrict__ lng,
                      const float* __restrict__ lnb) {
    int wid = threadIdx.x >> 5, lane = threadIdx.x & 31;
    int i = blockIdx.x * 8 + wid;
    int deg = min(g_cnt[i], BCAP);
    float si = g_s_src[i];

    float4 a0 = make_float4(0.f, 0.f, 0.f, 0.f);
    float4 a1 = make_float4(0.f, 0.f, 0.f, 0.f);
    float wsum = 0.f;

    for (int base = 0; base < deg; base += 32) {
        int idx = base + lane;
        int tg = 0;
        float w = 0.f;
        if (idx < deg) {
            tg = g_bkt[i * BCAP + idx];
            float e = si + g_s_tgt[tg];
            e = (e > 0.f) ? e : 0.2f * e;
            w = expf(e) - 1.f;
        }
        float wr = w;
#pragma unroll
        for (int o = 16; o; o >>= 1) wr += __shfl_xor_sync(0xffffffffu, wr, o);
        wsum += wr;
        int len = min(32, deg - base);
        for (int k = 0; k < len; k++) {
            float wk = __shfl_sync(0xffffffffu, w, k);
            int   tk = __shfl_sync(0xffffffffu, tg, k);
            uint4 u = *((const uint4*)(g_hwb + (size_t)tk * HH) + lane);
            float4 v0 = unp_bf4u(u.x, u.y);
            float4 v1 = unp_bf4u(u.z, u.w);
            a0.x = fmaf(wk, v0.x, a0.x); a0.y = fmaf(wk, v0.y, a0.y);
            a0.z = fmaf(wk, v0.z, a0.z); a0.w = fmaf(wk, v0.w, a0.w);
            a1.x = fmaf(wk, v1.x, a1.x); a1.y = fmaf(wk, v1.y, a1.y);
            a1.z = fmaf(wk, v1.z, a1.z); a1.w = fmaf(wk, v1.w, a1.w);
        }
    }
    float denom = (float)NN + wsum;

    float4 cs0 = *((const float4*)g_colsum + lane * 2);
    float4 cs1 = *((const float4*)g_colsum + lane * 2 + 1);
    float4 h0 = *((const float4*)(h + (size_t)i * HH) + lane * 2);
    float4 h1 = *((const float4*)(h + (size_t)i * HH) + lane * 2 + 1);
    float4 v0, v1;
    v0.x = h0.x + (cs0.x + a0.x) / denom;
    v0.y = h0.y + (cs0.y + a0.y) / denom;
    v0.z = h0.z + (cs0.z + a0.z) / denom;
    v0.w = h0.w + (cs0.w + a0.w) / denom;
    v1.x = h1.x + (cs1.x + a1.x) / denom;
    v1.y = h1.y + (cs1.y + a1.y) / denom;
    v1.z = h1.z + (cs1.z + a1.z) / denom;
    v1.w = h1.w + (cs1.w + a1.w) / denom;

    float ts = v0.x + v0.y + v0.z + v0.w + v1.x + v1.y + v1.z + v1.w;
#pragma unroll
    for (int o = 16; o; o >>= 1) ts += __shfl_xor_sync(0xffffffffu, ts, o);
    float mu = ts / (float)HH;
    float d0x = v0.x - mu, d0y = v0.y - mu, d0z = v0.z - mu, d0w = v0.w - mu;
    float d1x = v1.x - mu, d1y = v1.y - mu, d1z = v1.z - mu, d1w = v1.w - mu;
    float tv = d0x * d0x + d0y * d0y + d0z * d0z + d0w * d0w
             + d1x * d1x + d1y * d1y + d1z * d1z + d1w * d1w;
#pragma unroll
    for (int o = 16; o; o >>= 1) tv += __shfl_xor_sync(0xffffffffu, tv, o);
    float rs = rsqrtf(tv / (float)HH + LN_EPS);

    float4 g0 = *((const float4*)lng + lane * 2);
    float4 g1 = *((const float4*)lng + lane * 2 + 1);
    float4 b0 = *((const float4*)lnb + lane * 2);
    float4 b1 = *((const float4*)lnb + lane * 2 + 1);
    float y[8];
    y[0] = d0x * rs * g0.x + b0.x; y[1] = d0y * rs * g0.y + b0.y;
    y[2] = d0z * rs * g0.z + b0.z; y[3] = d0w * rs * g0.w + b0.w;
    y[4] = d1x * rs * g1.x + b1.x; y[5] = d1y * rs * g1.y + b1.y;
    y[6] = d1z * rs * g1.z + b1.z; y[7] = d1w * rs * g1.w + b1.w;
#pragma unroll
    for (int j = 0; j < 8; j++) y[j] = (y[j] > 0.f) ? y[j] : (expf(y[j]) - 1.f);

    float4 o0 = make_float4(y[0], y[1], y[2], y[3]);
    float4 o1 = make_float4(y[4], y[5], y[6], y[7]);
    *((float4*)(h + (size_t)i * HH) + lane * 2)     = o0;
    *((float4*)(h + (size_t)i * HH) + lane * 2 + 1) = o1;

    uint32_t hiw[4], low[4];
#pragma unroll
    for (int p = 0; p < 4; p++) {
        __nv_bfloat16 h0b = __float2bfloat16(y[2 * p]);
        __nv_bfloat16 h1b = __float2bfloat16(y[2 * p + 1]);
        float l0 = y[2 * p] - __bfloat162float(h0b);
        float l1 = y[2 * p + 1] - __bfloat162float(h1b);
        __nv_bfloat162 hp = __nv_bfloat162(h0b, h1b);
        __nv_bfloat162 lp = __nv_bfloat162(__float2bfloat16(l0), __float2bfloat16(l1));
        hiw[p] = *reinterpret_cast<uint32_t*>(&hp);
        low[p] = *reinterpret_cast<uint32_t*>(&lp);
    }
    *((uint4*)(g_Ah2 + (size_t)i * HH) + lane) = make_uint4(hiw[0], hiw[1], hiw[2], hiw[3]);
    *((uint4*)(g_Al2 + (size_t)i * HH) + lane) = make_uint4(low[0], low[1], low[2], low[3]);
}

// ---------------- gated pooling ------------------------------------------
__global__ void pool1_kernel(const float* __restrict__ h,
                             const float* __restrict__ Wp,
                             const float* __restrict__ bp) {
    __shared__ float gates[128];
    int b = blockIdx.x;
    int t = threadIdx.x;
    int warp = t >> 5, lane = t & 31;
    int base = b * 128;
    for (int it = 0; it < 16; it++) {
        int n = base + warp * 16 + it;
        const float* row = h + (size_t)n * HH;
        float s = 0.f;
        for (int j = lane; j < HH; j += 32) s += row[j] * Wp[j];
#pragma unroll
        for (int o = 16; o; o >>= 1) s += __shfl_xor_sync(0xffffffffu, s, o);
        if (lane == 0) gates[warp * 16 + it] = 1.f / (1.f + expf(-(s + bp[0])));
    }
    __syncthreads();
    int c = t;
    float s = 0.f;
    for (int ln = 0; ln < 128; ln++)
        s = fmaf(gates[ln], h[(size_t)(base + ln) * HH + c], s);
    g_pool_part[b * HH + c] = s;
}
__global__ void pool2_kernel(float* __restrict__ emb) {
    int c = threadIdx.x;
    float s = 0.f;
#pragma unroll
    for (int b = 0; b < 64; b++) s += g_pool_part[b * HH + c];
    emb[c] = s;
}

// ---------------- launch --------------------------------------------------
extern "C" void kernel_launch(void* const* d_in, const int* in_sizes, int n_in,
                              void* d_out, int out_size) {
    const float* x      = (const float*)d_in[0];
    const int*   ei     = (const int*)d_in[1];
    const float* W_in   = (const float*)d_in[2];
    const float* b_in   = (const float*)d_in[3];
    const float* W_gat  = (const float*)d_in[4];
    const float* a_gat  = (const float*)d_in[5];
    const float* ln_g   = (const float*)d_in[6];
    const float* ln_b   = (const float*)d_in[7];
    const float* W_pool = (const float*)d_in[8];
    const float* b_pool = (const float*)d_in[9];

    float* out = (float*)d_out;
    float* h   = out;

    __nv_bfloat16 *Ah, *Al, *Ah2, *Al2, *Bh, *Bl, *hwb;
    cudaGetSymbolAddress((void**)&Ah,  g_Ah);
    cudaGetSymbolAddress((void**)&Al,  g_Al);
    cudaGetSymbolAddress((void**)&Ah2, g_Ah2);
    cudaGetSymbolAddress((void**)&Al2, g_Al2);
    cudaGetSymbolAddress((void**)&Bh,  g_Bh);
    cudaGetSymbolAddress((void**)&Bl,  g_Bl);
    cudaGetSymbolAddress((void**)&hwb, g_hwb);

    cudaFuncSetAttribute(gemm_mma, cudaFuncAttributeMaxDynamicSharedMemorySize, SMEM_DYN);

    prep_kernel<<<2048, 256>>>(x, W_in, W_gat);
    scatter_kernel<<<256, 256>>>(ei);
    sort_bkt_kernel<<<NN / 8, 256>>>();

    // h = x @ W_in^T + b_in; emit h split for layer GEMMs
    gemm_mma<<<dim3(64, 4), 256, SMEM_DYN>>>(Ah, Al, Bh, Bl, b_in, h, Ah2, Al2,
                                             (__nv_bfloat16*)nullptr, nullptr, D_IN);

    for (int l = 0; l < NL; l++) {
        const __nv_bfloat16* Wh = Bh + D_IN * HH + (size_t)l * HH * HH;
        const __nv_bfloat16* Wl = Bl + D_IN * HH + (size_t)l * HH * HH;
        gemm_mma<<<dim3(64, 4), 256, SMEM_DYN>>>(Ah2, Al2, Wh, Wl, nullptr, nullptr,
                                                 (__nv_bfloat16*)nullptr,
                                                 (__nv_bfloat16*)nullptr, hwb,
                                                 a_gat + (size_t)l * 2 * HH, HH);
        finalize_kernel<<<1 + NN / 256, 256>>>();
        aggregate_kernel<<<NN / 8, 256>>>(h, ln_g + (size_t)l * HH,
                                          ln_b + (size_t)l * HH);
    }

    pool1_kernel<<<64, 256>>>(h, W_pool, b_pool);
    pool2_kernel<<<1, 256>>>(out + (size_t)NN * HH);
}